// round 6
// baseline (speedup 1.0000x reference)
#include <cuda_runtime.h>

// Problem constants
#define BATCH 8
#define SEQ   1024
#define DIM   1024
#define NHEAD 16
#define HDIM  64

// Scratch layout (element offsets into g_scratch)
#define QOFF 0
#define KOFF (8u * 1024u * 1024u)
#define VOFF (16u * 1024u * 1024u)
#define POFF (24u * 1024u * 1024u)

// 128 MB static device scratch (allocation-free per harness rules)
__device__ float g_scratch[32u * 1024u * 1024u];

// SGEMM tiling
#define BM 128
#define BN 128
#define BK 8

// ---------------------------------------------------------------------------
// Kernel 1: projection GEMM with bias + scale.
//   C[m,n] = alpha * (sum_k A[m,k] * W[k,n] + bias[n])
//   A: (8192 x 1024) row-major (input), W: (1024 x 1024) row-major,
//   C -> g_scratch + c_off.
// ---------------------------------------------------------------------------
__global__ __launch_bounds__(256, 2)
void proj_gemm(const float* __restrict__ A, const float* __restrict__ W,
               const float* __restrict__ bias, unsigned c_off, float alpha) {
    __shared__ float As[BK][BM];
    __shared__ float Bs[BK][BN];
    const int K = DIM, N = DIM;

    int tid = threadIdx.x;
    int tx = tid & 15;        // 0..15 -> 8 output cols each
    int ty = tid >> 4;        // 0..15 -> 8 output rows each
    int bm = blockIdx.y * BM;
    int bn = blockIdx.x * BN;

    // A tile loader: 128 rows x 8 k-cols; thread loads one float4
    int arow = tid >> 1;           // 0..127
    int acol = (tid & 1) * 4;      // 0 or 4
    // W tile loader: 8 k-rows x 128 n-cols
    int wrow = tid >> 5;           // 0..7
    int wcol = (tid & 31) * 4;     // 0..124

    const float* Ap = A + (size_t)(bm + arow) * K + acol;
    const float* Wp = W + (size_t)wrow * N + bn + wcol;

    float acc[8][8];
#pragma unroll
    for (int i = 0; i < 8; i++)
#pragma unroll
        for (int j = 0; j < 8; j++) acc[i][j] = 0.0f;

    for (int k0 = 0; k0 < K; k0 += BK) {
        float4 av = *(const float4*)Ap; Ap += BK;
        float4 wv = *(const float4*)Wp; Wp += (size_t)BK * N;
        __syncthreads();
        As[acol + 0][arow] = av.x;
        As[acol + 1][arow] = av.y;
        As[acol + 2][arow] = av.z;
        As[acol + 3][arow] = av.w;
        *(float4*)&Bs[wrow][wcol] = wv;
        __syncthreads();
#pragma unroll
        for (int kk = 0; kk < BK; ++kk) {
            float a[8], b[8];
#pragma unroll
            for (int i = 0; i < 8; i++) a[i] = As[kk][ty * 8 + i];
#pragma unroll
            for (int j = 0; j < 8; j++) b[j] = Bs[kk][tx * 8 + j];
#pragma unroll
            for (int i = 0; i < 8; i++)
#pragma unroll
                for (int j = 0; j < 8; j++)
                    acc[i][j] += a[i] * b[j];
        }
    }

    float* C = g_scratch + c_off;
    int n0 = bn + tx * 8;
    float bb[8];
#pragma unroll
    for (int j = 0; j < 8; j++) bb[j] = bias[n0 + j];
#pragma unroll
    for (int i = 0; i < 8; i++) {
        int m = bm + ty * 8 + i;
        float4 v0, v1;
        v0.x = alpha * (acc[i][0] + bb[0]);
        v0.y = alpha * (acc[i][1] + bb[1]);
        v0.z = alpha * (acc[i][2] + bb[2]);
        v0.w = alpha * (acc[i][3] + bb[3]);
        v1.x = alpha * (acc[i][4] + bb[4]);
        v1.y = alpha * (acc[i][5] + bb[5]);
        v1.z = alpha * (acc[i][6] + bb[6]);
        v1.w = alpha * (acc[i][7] + bb[7]);
        *(float4*)(C + (size_t)m * N + n0)     = v0;
        *(float4*)(C + (size_t)m * N + n0 + 4) = v1;
    }
}

// ---------------------------------------------------------------------------
// Kernel 2: batched scores GEMM (NT):
//   P[b][i][j] = sum_d Q[b][i][d] * K[b][j][d]   (1/8 already folded into Q)
// ---------------------------------------------------------------------------
__global__ __launch_bounds__(256, 2)
void scores_gemm() {
    __shared__ float As[BK][BM];
    __shared__ float Bs[BK][BN];
    const int K = DIM;

    int bz = blockIdx.z;
    const float* A  = g_scratch + QOFF + (size_t)bz * SEQ * DIM;
    const float* Bm = g_scratch + KOFF + (size_t)bz * SEQ * DIM;
    float*       C  = g_scratch + POFF + (size_t)bz * SEQ * SEQ;

    int tid = threadIdx.x;
    int tx = tid & 15, ty = tid >> 4;
    int bm = blockIdx.y * BM, bn = blockIdx.x * BN;

    int arow = tid >> 1;
    int acol = (tid & 1) * 4;

    const float* Ap = A  + (size_t)(bm + arow) * K + acol;
    const float* Bp = Bm + (size_t)(bn + arow) * K + acol;  // NT: B rows are n-index

    float acc[8][8];
#pragma unroll
    for (int i = 0; i < 8; i++)
#pragma unroll
        for (int j = 0; j < 8; j++) acc[i][j] = 0.0f;

    for (int k0 = 0; k0 < K; k0 += BK) {
        float4 av = *(const float4*)Ap; Ap += BK;
        float4 bv = *(const float4*)Bp; Bp += BK;
        __syncthreads();
        As[acol + 0][arow] = av.x;
        As[acol + 1][arow] = av.y;
        As[acol + 2][arow] = av.z;
        As[acol + 3][arow] = av.w;
        Bs[acol + 0][arow] = bv.x;
        Bs[acol + 1][arow] = bv.y;
        Bs[acol + 2][arow] = bv.z;
        Bs[acol + 3][arow] = bv.w;
        __syncthreads();
#pragma unroll
        for (int kk = 0; kk < BK; ++kk) {
            float a[8], b[8];
#pragma unroll
            for (int i = 0; i < 8; i++) a[i] = As[kk][ty * 8 + i];
#pragma unroll
            for (int j = 0; j < 8; j++) b[j] = Bs[kk][tx * 8 + j];
#pragma unroll
            for (int i = 0; i < 8; i++)
#pragma unroll
                for (int j = 0; j < 8; j++)
                    acc[i][j] += a[i] * b[j];
        }
    }

    int n0 = bn + tx * 8;
#pragma unroll
    for (int i = 0; i < 8; i++) {
        int m = bm + ty * 8 + i;
        float4 v0 = make_float4(acc[i][0], acc[i][1], acc[i][2], acc[i][3]);
        float4 v1 = make_float4(acc[i][4], acc[i][5], acc[i][6], acc[i][7]);
        *(float4*)(C + (size_t)m * SEQ + n0)     = v0;
        *(float4*)(C + (size_t)m * SEQ + n0 + 4) = v1;
    }
}

// ---------------------------------------------------------------------------
// Kernel 3: masked softmax over rows of P (in place).
//   s += (1 - mask) * -1e9; p = softmax(s)
// One block (256 threads) per row of 1024; each thread owns one float4.
// ---------------------------------------------------------------------------
__global__ __launch_bounds__(256)
void softmax_kernel(const float* __restrict__ mask) {
    __shared__ float red[8];
    float* P = g_scratch + POFF;
    int row = blockIdx.x;                 // b*SEQ + q
    int b   = row >> 10;
    int q   = row & (SEQ - 1);
    float* p = P + (size_t)row * SEQ;
    const float* mrow = mask + ((size_t)b * SEQ + q) * SEQ;

    int t = threadIdx.x;
    float4 s  = ((const float4*)p)[t];
    float4 mm = ((const float4*)mrow)[t];
    s.x += (1.0f - mm.x) * -1e9f;
    s.y += (1.0f - mm.y) * -1e9f;
    s.z += (1.0f - mm.z) * -1e9f;
    s.w += (1.0f - mm.w) * -1e9f;

    // block max
    float v = fmaxf(fmaxf(s.x, s.y), fmaxf(s.z, s.w));
#pragma unroll
    for (int o = 16; o; o >>= 1) v = fmaxf(v, __shfl_xor_sync(0xffffffffu, v, o));
    if ((t & 31) == 0) red[t >> 5] = v;
    __syncthreads();
    if (t < 32) {
        float x = (t < 8) ? red[t] : -3.4e38f;
#pragma unroll
        for (int o = 4; o; o >>= 1) x = fmaxf(x, __shfl_xor_sync(0xffffffffu, x, o));
        if (t == 0) red[0] = x;
    }
    __syncthreads();
    float rmax = red[0];

    float e0 = expf(s.x - rmax);
    float e1 = expf(s.y - rmax);
    float e2 = expf(s.z - rmax);
    float e3 = expf(s.w - rmax);

    __syncthreads();  // done reading red[0] before reuse
    float sum = e0 + e1 + e2 + e3;
#pragma unroll
    for (int o = 16; o; o >>= 1) sum += __shfl_xor_sync(0xffffffffu, sum, o);
    if ((t & 31) == 0) red[t >> 5] = sum;
    __syncthreads();
    if (t < 32) {
        float x = (t < 8) ? red[t] : 0.0f;
#pragma unroll
        for (int o = 4; o; o >>= 1) x += __shfl_xor_sync(0xffffffffu, x, o);
        if (t == 0) red[0] = x;
    }
    __syncthreads();
    float inv = 1.0f / red[0];

    ((float4*)p)[t] = make_float4(e0 * inv, e1 * inv, e2 * inv, e3 * inv);
}

// ---------------------------------------------------------------------------
// Kernel 4: batched ctx GEMM (NN) with permuted output:
//   ctx[b][q][n] = sum_j P[b][q][j] * V[b][j][n]
//   out[b*S*D + (n/64)*S*64 + q*64 + (n%64)] = ctx[b][q][n]
// ---------------------------------------------------------------------------
__global__ __launch_bounds__(256, 2)
void ctx_gemm(float* __restrict__ out) {
    __shared__ float As[BK][BM];
    __shared__ float Bs[BK][BN];
    const int K = SEQ, N = DIM;

    int bz = blockIdx.z;
    const float* A = g_scratch + POFF + (size_t)bz * SEQ * SEQ;
    const float* V = g_scratch + VOFF + (size_t)bz * SEQ * DIM;

    int tid = threadIdx.x;
    int tx = tid & 15, ty = tid >> 4;
    int bm = blockIdx.y * BM, bn = blockIdx.x * BN;

    int arow = tid >> 1;
    int acol = (tid & 1) * 4;
    int vrow = tid >> 5;
    int vcol = (tid & 31) * 4;

    const float* Ap = A + (size_t)(bm + arow) * K + acol;
    const float* Vp = V + (size_t)vrow * N + bn + vcol;

    float acc[8][8];
#pragma unroll
    for (int i = 0; i < 8; i++)
#pragma unroll
        for (int j = 0; j < 8; j++) acc[i][j] = 0.0f;

    for (int k0 = 0; k0 < K; k0 += BK) {
        float4 av = *(const float4*)Ap; Ap += BK;
        float4 vv = *(const float4*)Vp; Vp += (size_t)BK * N;
        __syncthreads();
        As[acol + 0][arow] = av.x;
        As[acol + 1][arow] = av.y;
        As[acol + 2][arow] = av.z;
        As[acol + 3][arow] = av.w;
        *(float4*)&Bs[vrow][vcol] = vv;
        __syncthreads();
#pragma unroll
        for (int kk = 0; kk < BK; ++kk) {
            float a[8], b[8];
#pragma unroll
            for (int i = 0; i < 8; i++) a[i] = As[kk][ty * 8 + i];
#pragma unroll
            for (int j = 0; j < 8; j++) b[j] = Bs[kk][tx * 8 + j];
#pragma unroll
            for (int i = 0; i < 8; i++)
#pragma unroll
                for (int j = 0; j < 8; j++)
                    acc[i][j] += a[i] * b[j];
        }
    }

    // Permuted epilogue. Each thread's 8 cols are [n0, n0+7], n0 % 8 == 0,
    // so they live in a single head h = n0/64, dh = n0%64 .. +7.
    int n0 = bn + tx * 8;
    int h  = n0 >> 6;
    int dh = n0 & 63;
    float* obase = out + (size_t)bz * SEQ * DIM + (size_t)h * SEQ * HDIM + dh;
#pragma unroll
    for (int i = 0; i < 8; i++) {
        int m = bm + ty * 8 + i;
        float4 v0 = make_float4(acc[i][0], acc[i][1], acc[i][2], acc[i][3]);
        float4 v1 = make_float4(acc[i][4], acc[i][5], acc[i][6], acc[i][7]);
        *(float4*)(obase + (size_t)m * HDIM)     = v0;
        *(float4*)(obase + (size_t)m * HDIM + 4) = v1;
    }
}

// ---------------------------------------------------------------------------
// Launch
// ---------------------------------------------------------------------------
extern "C" void kernel_launch(void* const* d_in, const int* in_sizes, int n_in,
                              void* d_out, int out_size) {
    const float* hidden = (const float*)d_in[0];
    const float* right  = (const float*)d_in[1];
    const float* mask   = (const float*)d_in[2];
    const float* Wq     = (const float*)d_in[3];
    const float* bq     = (const float*)d_in[4];
    const float* Wk     = (const float*)d_in[5];
    const float* bk     = (const float*)d_in[6];
    const float* Wv     = (const float*)d_in[7];
    const float* bv     = (const float*)d_in[8];
    float* out = (float*)d_out;

    dim3 gproj(DIM / BN, (BATCH * SEQ) / BM);      // (8, 64)
    dim3 gbat(SEQ / BN, SEQ / BM, BATCH);          // (8, 8, 8)

    // Fold 1/sqrt(64) = 0.125 (exact power of two) into Q.
    proj_gemm<<<gproj, 256>>>(hidden, Wq, bq, QOFF, 0.125f);
    proj_gemm<<<gproj, 256>>>(right,  Wk, bk, KOFF, 1.0f);
    proj_gemm<<<gproj, 256>>>(right,  Wv, bv, VOFF, 1.0f);
    scores_gemm<<<gbat, 256>>>();
    softmax_kernel<<<BATCH * SEQ, 256>>>(mask);
    ctx_gemm<<<gbat, 256>>>(out);
}

// round 7
// speedup vs baseline: 1.0048x; 1.0048x over previous
#include <cuda_runtime.h>

// Problem constants
#define BATCH 8
#define SEQ   1024
#define DIM   1024
#define NHEAD 16
#define HDIM  64

// Scratch layout (element offsets into g_scratch)
#define QOFF 0
#define KOFF (8u * 1024u * 1024u)
#define VOFF (16u * 1024u * 1024u)
#define POFF (24u * 1024u * 1024u)

// 128 MB static device scratch (allocation-free per harness rules)
__device__ float g_scratch[32u * 1024u * 1024u];

// SGEMM tiling
#define BM 128
#define BN 128
#define BK 8

// ---------------------------------------------------------------------------
// Kernel 1: projection GEMM with bias + scale.
//   C[m,n] = alpha * (sum_k A[m,k] * W[k,n] + bias[n])
//   A: (8192 x 1024) row-major (input), W: (1024 x 1024) row-major,
//   C -> g_scratch + c_off.
// ---------------------------------------------------------------------------
__global__ __launch_bounds__(256, 2)
void proj_gemm(const float* __restrict__ A, const float* __restrict__ W,
               const float* __restrict__ bias, unsigned c_off, float alpha) {
    __shared__ float As[BK][BM];
    __shared__ float Bs[BK][BN];
    const int K = DIM, N = DIM;

    int tid = threadIdx.x;
    int tx = tid & 15;        // 0..15 -> 8 output cols each
    int ty = tid >> 4;        // 0..15 -> 8 output rows each
    int bm = blockIdx.y * BM;
    int bn = blockIdx.x * BN;

    // A tile loader: 128 rows x 8 k-cols; thread loads one float4
    int arow = tid >> 1;           // 0..127
    int acol = (tid & 1) * 4;      // 0 or 4
    // W tile loader: 8 k-rows x 128 n-cols
    int wrow = tid >> 5;           // 0..7
    int wcol = (tid & 31) * 4;     // 0..124

    const float* Ap = A + (size_t)(bm + arow) * K + acol;
    const float* Wp = W + (size_t)wrow * N + bn + wcol;

    float acc[8][8];
#pragma unroll
    for (int i = 0; i < 8; i++)
#pragma unroll
        for (int j = 0; j < 8; j++) acc[i][j] = 0.0f;

    for (int k0 = 0; k0 < K; k0 += BK) {
        float4 av = *(const float4*)Ap; Ap += BK;
        float4 wv = *(const float4*)Wp; Wp += (size_t)BK * N;
        __syncthreads();
        As[acol + 0][arow] = av.x;
        As[acol + 1][arow] = av.y;
        As[acol + 2][arow] = av.z;
        As[acol + 3][arow] = av.w;
        *(float4*)&Bs[wrow][wcol] = wv;
        __syncthreads();
#pragma unroll
        for (int kk = 0; kk < BK; ++kk) {
            float a[8], b[8];
#pragma unroll
            for (int i = 0; i < 8; i++) a[i] = As[kk][ty * 8 + i];
#pragma unroll
            for (int j = 0; j < 8; j++) b[j] = Bs[kk][tx * 8 + j];
#pragma unroll
            for (int i = 0; i < 8; i++)
#pragma unroll
                for (int j = 0; j < 8; j++)
                    acc[i][j] += a[i] * b[j];
        }
    }

    float* C = g_scratch + c_off;
    int n0 = bn + tx * 8;
    float bb[8];
#pragma unroll
    for (int j = 0; j < 8; j++) bb[j] = bias[n0 + j];
#pragma unroll
    for (int i = 0; i < 8; i++) {
        int m = bm + ty * 8 + i;
        float4 v0, v1;
        v0.x = alpha * (acc[i][0] + bb[0]);
        v0.y = alpha * (acc[i][1] + bb[1]);
        v0.z = alpha * (acc[i][2] + bb[2]);
        v0.w = alpha * (acc[i][3] + bb[3]);
        v1.x = alpha * (acc[i][4] + bb[4]);
        v1.y = alpha * (acc[i][5] + bb[5]);
        v1.z = alpha * (acc[i][6] + bb[6]);
        v1.w = alpha * (acc[i][7] + bb[7]);
        *(float4*)(C + (size_t)m * N + n0)     = v0;
        *(float4*)(C + (size_t)m * N + n0 + 4) = v1;
    }
}

// ---------------------------------------------------------------------------
// Kernel 2: batched scores GEMM (NT):
//   P[b][i][j] = sum_d Q[b][i][d] * K[b][j][d]   (1/8 already folded into Q)
// ---------------------------------------------------------------------------
__global__ __launch_bounds__(256, 2)
void scores_gemm() {
    __shared__ float As[BK][BM];
    __shared__ float Bs[BK][BN];
    const int K = DIM;

    int bz = blockIdx.z;
    const float* A  = g_scratch + QOFF + (size_t)bz * SEQ * DIM;
    const float* Bm = g_scratch + KOFF + (size_t)bz * SEQ * DIM;
    float*       C  = g_scratch + POFF + (size_t)bz * SEQ * SEQ;

    int tid = threadIdx.x;
    int tx = tid & 15, ty = tid >> 4;
    int bm = blockIdx.y * BM, bn = blockIdx.x * BN;

    int arow = tid >> 1;
    int acol = (tid & 1) * 4;

    const float* Ap = A  + (size_t)(bm + arow) * K + acol;
    const float* Bp = Bm + (size_t)(bn + arow) * K + acol;  // NT: B rows are n-index

    float acc[8][8];
#pragma unroll
    for (int i = 0; i < 8; i++)
#pragma unroll
        for (int j = 0; j < 8; j++) acc[i][j] = 0.0f;

    for (int k0 = 0; k0 < K; k0 += BK) {
        float4 av = *(const float4*)Ap; Ap += BK;
        float4 bv = *(const float4*)Bp; Bp += BK;
        __syncthreads();
        As[acol + 0][arow] = av.x;
        As[acol + 1][arow] = av.y;
        As[acol + 2][arow] = av.z;
        As[acol + 3][arow] = av.w;
        Bs[acol + 0][arow] = bv.x;
        Bs[acol + 1][arow] = bv.y;
        Bs[acol + 2][arow] = bv.z;
        Bs[acol + 3][arow] = bv.w;
        __syncthreads();
#pragma unroll
        for (int kk = 0; kk < BK; ++kk) {
            float a[8], b[8];
#pragma unroll
            for (int i = 0; i < 8; i++) a[i] = As[kk][ty * 8 + i];
#pragma unroll
            for (int j = 0; j < 8; j++) b[j] = Bs[kk][tx * 8 + j];
#pragma unroll
            for (int i = 0; i < 8; i++)
#pragma unroll
                for (int j = 0; j < 8; j++)
                    acc[i][j] += a[i] * b[j];
        }
    }

    int n0 = bn + tx * 8;
#pragma unroll
    for (int i = 0; i < 8; i++) {
        int m = bm + ty * 8 + i;
        float4 v0 = make_float4(acc[i][0], acc[i][1], acc[i][2], acc[i][3]);
        float4 v1 = make_float4(acc[i][4], acc[i][5], acc[i][6], acc[i][7]);
        *(float4*)(C + (size_t)m * SEQ + n0)     = v0;
        *(float4*)(C + (size_t)m * SEQ + n0 + 4) = v1;
    }
}

// ---------------------------------------------------------------------------
// Kernel 3: masked softmax over rows of P (in place).
//   s += (1 - mask) * -1e9; p = softmax(s)
// One block (256 threads) per row of 1024; each thread owns one float4.
// ---------------------------------------------------------------------------
__global__ __launch_bounds__(256)
void softmax_kernel(const float* __restrict__ mask) {
    __shared__ float red[8];
    float* P = g_scratch + POFF;
    int row = blockIdx.x;                 // b*SEQ + q
    int b   = row >> 10;
    int q   = row & (SEQ - 1);
    float* p = P + (size_t)row * SEQ;
    const float* mrow = mask + ((size_t)b * SEQ + q) * SEQ;

    int t = threadIdx.x;
    float4 s  = ((const float4*)p)[t];
    float4 mm = ((const float4*)mrow)[t];
    s.x += (1.0f - mm.x) * -1e9f;
    s.y += (1.0f - mm.y) * -1e9f;
    s.z += (1.0f - mm.z) * -1e9f;
    s.w += (1.0f - mm.w) * -1e9f;

    // block max
    float v = fmaxf(fmaxf(s.x, s.y), fmaxf(s.z, s.w));
#pragma unroll
    for (int o = 16; o; o >>= 1) v = fmaxf(v, __shfl_xor_sync(0xffffffffu, v, o));
    if ((t & 31) == 0) red[t >> 5] = v;
    __syncthreads();
    if (t < 32) {
        float x = (t < 8) ? red[t] : -3.4e38f;
#pragma unroll
        for (int o = 4; o; o >>= 1) x = fmaxf(x, __shfl_xor_sync(0xffffffffu, x, o));
        if (t == 0) red[0] = x;
    }
    __syncthreads();
    float rmax = red[0];

    float e0 = expf(s.x - rmax);
    float e1 = expf(s.y - rmax);
    float e2 = expf(s.z - rmax);
    float e3 = expf(s.w - rmax);

    __syncthreads();  // done reading red[0] before reuse
    float sum = e0 + e1 + e2 + e3;
#pragma unroll
    for (int o = 16; o; o >>= 1) sum += __shfl_xor_sync(0xffffffffu, sum, o);
    if ((t & 31) == 0) red[t >> 5] = sum;
    __syncthreads();
    if (t < 32) {
        float x = (t < 8) ? red[t] : 0.0f;
#pragma unroll
        for (int o = 4; o; o >>= 1) x += __shfl_xor_sync(0xffffffffu, x, o);
        if (t == 0) red[0] = x;
    }
    __syncthreads();
    float inv = 1.0f / red[0];

    ((float4*)p)[t] = make_float4(e0 * inv, e1 * inv, e2 * inv, e3 * inv);
}

// ---------------------------------------------------------------------------
// Kernel 4: batched ctx GEMM (NN) with permuted output:
//   ctx[b][q][n] = sum_j P[b][q][j] * V[b][j][n]
//   out[b*S*D + (n/64)*S*64 + q*64 + (n%64)] = ctx[b][q][n]
// ---------------------------------------------------------------------------
__global__ __launch_bounds__(256, 2)
void ctx_gemm(float* __restrict__ out) {
    __shared__ float As[BK][BM];
    __shared__ float Bs[BK][BN];
    const int K = SEQ, N = DIM;

    int bz = blockIdx.z;
    const float* A = g_scratch + POFF + (size_t)bz * SEQ * SEQ;
    const float* V = g_scratch + VOFF + (size_t)bz * SEQ * DIM;

    int tid = threadIdx.x;
    int tx = tid & 15, ty = tid >> 4;
    int bm = blockIdx.y * BM, bn = blockIdx.x * BN;

    int arow = tid >> 1;
    int acol = (tid & 1) * 4;
    int vrow = tid >> 5;
    int vcol = (tid & 31) * 4;

    const float* Ap = A + (size_t)(bm + arow) * K + acol;
    const float* Vp = V + (size_t)vrow * N + bn + vcol;

    float acc[8][8];
#pragma unroll
    for (int i = 0; i < 8; i++)
#pragma unroll
        for (int j = 0; j < 8; j++) acc[i][j] = 0.0f;

    for (int k0 = 0; k0 < K; k0 += BK) {
        float4 av = *(const float4*)Ap; Ap += BK;
        float4 vv = *(const float4*)Vp; Vp += (size_t)BK * N;
        __syncthreads();
        As[acol + 0][arow] = av.x;
        As[acol + 1][arow] = av.y;
        As[acol + 2][arow] = av.z;
        As[acol + 3][arow] = av.w;
        *(float4*)&Bs[vrow][vcol] = vv;
        __syncthreads();
#pragma unroll
        for (int kk = 0; kk < BK; ++kk) {
            float a[8], b[8];
#pragma unroll
            for (int i = 0; i < 8; i++) a[i] = As[kk][ty * 8 + i];
#pragma unroll
            for (int j = 0; j < 8; j++) b[j] = Bs[kk][tx * 8 + j];
#pragma unroll
            for (int i = 0; i < 8; i++)
#pragma unroll
                for (int j = 0; j < 8; j++)
                    acc[i][j] += a[i] * b[j];
        }
    }

    // Permuted epilogue. Each thread's 8 cols are [n0, n0+7], n0 % 8 == 0,
    // so they live in a single head h = n0/64, dh = n0%64 .. +7.
    int n0 = bn + tx * 8;
    int h  = n0 >> 6;
    int dh = n0 & 63;
    float* obase = out + (size_t)bz * SEQ * DIM + (size_t)h * SEQ * HDIM + dh;
#pragma unroll
    for (int i = 0; i < 8; i++) {
        int m = bm + ty * 8 + i;
        float4 v0 = make_float4(acc[i][0], acc[i][1], acc[i][2], acc[i][3]);
        float4 v1 = make_float4(acc[i][4], acc[i][5], acc[i][6], acc[i][7]);
        *(float4*)(obase + (size_t)m * HDIM)     = v0;
        *(float4*)(obase + (size_t)m * HDIM + 4) = v1;
    }
}

// ---------------------------------------------------------------------------
// Launch
// ---------------------------------------------------------------------------
extern "C" void kernel_launch(void* const* d_in, const int* in_sizes, int n_in,
                              void* d_out, int out_size) {
    const float* hidden = (const float*)d_in[0];
    const float* right  = (const float*)d_in[1];
    const float* mask   = (const float*)d_in[2];
    const float* Wq     = (const float*)d_in[3];
    const float* bq     = (const float*)d_in[4];
    const float* Wk     = (const float*)d_in[5];
    const float* bk     = (const float*)d_in[6];
    const float* Wv     = (const float*)d_in[7];
    const float* bv     = (const float*)d_in[8];
    float* out = (float*)d_out;

    dim3 gproj(DIM / BN, (BATCH * SEQ) / BM);      // (8, 64)
    dim3 gbat(SEQ / BN, SEQ / BM, BATCH);          // (8, 8, 8)

    // Fold 1/sqrt(64) = 0.125 (exact power of two) into Q.
    proj_gemm<<<gproj, 256>>>(hidden, Wq, bq, QOFF, 0.125f);
    proj_gemm<<<gproj, 256>>>(right,  Wk, bk, KOFF, 1.0f);
    proj_gemm<<<gproj, 256>>>(right,  Wv, bv, VOFF, 1.0f);
    scores_gemm<<<gbat, 256>>>();
    softmax_kernel<<<BATCH * SEQ, 256>>>(mask);
    ctx_gemm<<<gbat, 256>>>(out);
}